// round 7
// baseline (speedup 1.0000x reference)
#include <cuda_runtime.h>
#include <cuda.h>
#include <cstdint>

#define CIN   128
#define COUT  256
#define HW    56
#define HP    58
#define PIX   (HW*HW)
#define KTOT  1152
#define NB    32

#define TILE_H   4
#define BM       128
#define A_BYTES  16384            // one packed chunk: 128 rows x 128B
#define B_BYTES  44544            // 348 rows x 128B (6x58 halo)
#define B_STRIDE 45056            // 1024-aligned
#define SMEM_TOTAL (1024 + 3*A_BYTES + 2*B_STRIDE)   // 140288
#define NWARP    16

// g_Wt: fragment-packed weights, 72 chunks (t=0..35, z=0..1) x 4096 words.
// word idx: ((((chunk)*4 + ks)*8 + i8)*32 + lane)*4 + w
__device__ uint32_t g_Wt[COUT * KTOT];
__device__ uint32_t g_xp[NB * HP * HP * CIN];   // [b][hp][wp][c], tf32 bits

__device__ __forceinline__ uint32_t smem_u32(const void* p) {
    uint32_t a;
    asm("{ .reg .u64 t; cvta.to.shared.u64 t, %1; cvt.u32.u64 %0, t; }" : "=r"(a) : "l"(p));
    return a;
}
__device__ __forceinline__ uint32_t f2tf(float v) {
    uint32_t r; asm("cvt.rna.tf32.f32 %0, %1;" : "=r"(r) : "f"(v)); return r;
}

#define MBAR_INIT(a, c) asm volatile("mbarrier.init.shared.b64 [%0], %1;" :: "r"(a), "r"(c) : "memory")
#define MBAR_TX(a, b)   asm volatile("mbarrier.arrive.expect_tx.shared.b64 _, [%0], %1;" :: "r"(a), "r"(b) : "memory")
#define MBAR_ARRIVE(a)  asm volatile("mbarrier.arrive.shared.b64 _, [%0];" :: "r"(a) : "memory")
#define MBAR_WAIT(a, p) do {                                                    \
    uint32_t _m = (a), _p = (p), _d;                                            \
    asm volatile("{\n\t.reg .pred q;\n\t"                                       \
        "mbarrier.try_wait.parity.acquire.cta.shared::cta.b64 q, [%1], %2;\n\t" \
        "selp.b32 %0, 1, 0, q;\n\t}" : "=r"(_d) : "r"(_m), "r"(_p) : "memory"); \
    if (!_d) {                                                                  \
        asm volatile("{\n\t.reg .pred Q;\n\t"                                   \
        "WL_%=:\n\t"                                                            \
        "mbarrier.try_wait.parity.acquire.cta.shared::cta.b64 Q, [%0], %1, 0x989680;\n\t" \
        "@Q bra.uni WD_%=;\n\t"                                                 \
        "bra.uni WL_%=;\n\t"                                                    \
        "WD_%=:\n\t}" :: "r"(_m), "r"(_p) : "memory");                          \
    } } while (0)

#define TMA_2D(d, tm, c0, c1, mb)                                               \
    asm volatile("cp.async.bulk.tensor.2d.shared::cta.global.tile.mbarrier::complete_tx::bytes " \
        "[%0], [%1, {%2, %3}], [%4];" :: "r"(d), "l"(tm), "r"(c0), "r"(c1), "r"(mb) : "memory")
#define TMA_4D(d, tm, c0, c1, c2, c3, mb)                                       \
    asm volatile("cp.async.bulk.tensor.4d.shared::cta.global.tile.mbarrier::complete_tx::bytes " \
        "[%0], [%1, {%2, %3, %4, %5}], [%6];" :: "r"(d), "l"(tm), "r"(c0), "r"(c1), "r"(c2), "r"(c3), "r"(mb) : "memory")

// ---- prepass: W -> fragment-packed g_Wt ----
__global__ void wt_kernel(const float* __restrict__ W) {
    int idx = blockIdx.x * blockDim.x + threadIdx.x;
    if (idx >= COUT * KTOT) return;
    int w     = idx & 3;
    int lane  = (idx >> 2) & 31;
    int i8    = (idx >> 7) & 7;
    int ks    = (idx >> 10) & 3;
    int chunk = idx >> 12;
    int z = chunk & 1, t = chunk >> 1;
    int cc = t / 9, tap = t - cc * 9;
    int g = lane >> 2, tig = lane & 3;
    int m  = z * 128 + i8 * 16 + g + (w & 1) * 8;
    int kk = ks * 8 + tig + ((w >> 1) & 1) * 4;
    int c  = cc * 32 + kk;
    int dh = tap / 3, dw = tap - dh * 3;
    g_Wt[idx] = f2tf(W[((m * CIN + c) * 3 + dh) * 3 + dw]);
}
// ---- prepass: x[b][c][h][w] -> g_xp[b][h+1][w+1][c] (tf32, interior)
__global__ void xpad_kernel(const float* __restrict__ x) {
    __shared__ float sm[CIN * 57];
    int bx = blockIdx.x, b = bx / HW, h = bx - b * HW, tid = threadIdx.x;
    const float* xb = x + ((size_t)b * CIN) * PIX + h * HW;
    for (int i = tid; i < CIN * HW; i += 256) {
        int c = i / HW, w = i - c * HW;
        sm[c * 57 + w] = xb[c * PIX + w];
    }
    __syncthreads();
    uint32_t* xr = g_xp + ((size_t)(b * HP + h + 1)) * HP * CIN;
    for (int i = tid; i < HW * CIN; i += 256) {
        int w = i >> 7, c = i & 127;
        xr[(w + 1) * CIN + c] = f2tf(sm[c * 57 + w]);
    }
}
// ---- prepass: zero padded borders of g_xp
__global__ void xborder_kernel() {
    int idx = blockIdx.x * blockDim.x + threadIdx.x;
    if (idx >= NB * 228 * CIN) return;
    int c = idx & 127, r = idx >> 7, b = r / 228, cc = r - b * 228;
    int hp, wp;
    if (cc < 58)       { hp = 0;        wp = cc; }
    else if (cc < 116) { hp = 57;       wp = cc - 58; }
    else if (cc < 172) { hp = cc - 115; wp = 0; }
    else               { hp = cc - 171; wp = 57; }
    g_xp[((b * HP + hp) * HP + wp) * CIN + c] = 0u;
}

// ============================================================================
// Main: TMA-fed mma.sync tf32, fragment-packed A, 16 warps (32x56 warp tile).
//   CTA: M=128 (blockIdx.z half), N=224 (4 h-rows x 56 w), K = 4 cchunks x 9 taps
// ============================================================================
__global__ void __launch_bounds__(512, 1) conv_tc(
    const __grid_constant__ CUtensorMap tma_a,
    const __grid_constant__ CUtensorMap tma_b,
    float* __restrict__ out)
{
    extern __shared__ __align__(1024) uint8_t smem[];
    const uint32_t sb0 = smem_u32(smem);
    uint32_t* const smw = reinterpret_cast<uint32_t*>(smem);

    const int tid  = threadIdx.x;
    const int lane = tid & 31;
    const int g    = lane >> 2;
    const int tig  = lane & 3;
    const int warp = tid >> 5;
    const int wm   = warp >> 2;          // 0..3  (32-row m slice)
    const int wn   = warp & 3;           // 0..3  (h row)

    const int h0 = blockIdx.x * TILE_H;
    const int b  = blockIdx.y;
    const int z  = blockIdx.z;           // m half

    // barriers: afull[3]@0, aempty[3]@24, bfull[2]@48, bempty[2]@64
    if (tid == 0) {
        for (int s = 0; s < 3; s++) { MBAR_INIT(sb0 + 8*s, 1); MBAR_INIT(sb0 + 24 + 8*s, NWARP); }
        for (int s = 0; s < 2; s++) { MBAR_INIT(sb0 + 48 + 8*s, 1); MBAR_INIT(sb0 + 64 + 8*s, NWARP); }
    }
    __syncthreads();

    if (tid == 0) {   // prologue: A chunks 0,1 ; B chunk 0
        MBAR_TX(sb0 + 0, A_BYTES);
        TMA_2D(sb0 + 1024, &tma_a, 0, (0*2 + z) * 128, sb0 + 0);
        MBAR_TX(sb0 + 8, A_BYTES);
        TMA_2D(sb0 + 1024 + A_BYTES, &tma_a, 0, (1*2 + z) * 128, sb0 + 8);
        MBAR_TX(sb0 + 48, B_BYTES);
        TMA_4D(sb0 + 1024 + 3*A_BYTES, &tma_b, 0, 0, h0, b, sb0 + 48);
    }

    float acc[2][7][4];
#pragma unroll
    for (int i = 0; i < 2; i++)
#pragma unroll
        for (int j = 0; j < 7; j++)
#pragma unroll
            for (int e = 0; e < 4; e++) acc[i][j][e] = 0.f;

    uint4    af[2][2];
    uint32_t bf[2][7][2];

    for (int cc = 0; cc < 4; cc++) {
        if (tid == 0 && cc + 1 < 4) {       // prefetch next B halo
            const int u = cc + 1, s = u & 1;
            MBAR_WAIT(sb0 + 64 + 8*s, (u == 1) ? 1 : 0);
            MBAR_TX(sb0 + 48 + 8*s, B_BYTES);
            TMA_4D(sb0 + 1024 + 3*A_BYTES + s*B_STRIDE, &tma_b, u*32, 0, h0, b, sb0 + 48 + 8*s);
        }
        MBAR_WAIT(sb0 + 48 + 8*(cc & 1), (cc >> 1) & 1);
        const uint32_t* Bb = smw + 256 + 3*(A_BYTES/4) + (cc & 1)*(B_STRIDE/4);

        for (int tap = 0; tap < 9; tap++) {
            const int t = cc * 9 + tap;
            if (tid == 0 && t + 2 < 36) {    // prefetch A chunk t+2
                const int u = t + 2, s = u % 3;
                MBAR_WAIT(sb0 + 24 + 8*s, 1 ^ ((u / 3) & 1));
                MBAR_TX(sb0 + 8*s, A_BYTES);
                TMA_2D(sb0 + 1024 + s*A_BYTES, &tma_a, 0, (u*2 + z) * 128, sb0 + 8*s);
            }
            const int sA = t % 3;
            MBAR_WAIT(sb0 + 8*sA, (t / 3) & 1);
            const uint4* A4 = reinterpret_cast<const uint4*>(smw + 256 + sA * (A_BYTES/4));

            const int dh = tap / 3, dw = tap - dh * 3;
            const int rb2 = (wn + dh) * 58 + dw + g;   // B halo row for this lane
            const int mb  = 4 * (rb2 & 7);             // B swizzle xor

            auto loadFrags = [&](int ks, int pb) {
#pragma unroll
                for (int i = 0; i < 2; i++)
                    af[pb][i] = A4[(ks * 8 + wm * 2 + i) * 32 + lane];
                const int kb = 8 * ks;
                const int kB0 = (kb + tig) ^ mb, kB1 = (kb + tig + 4) ^ mb;
#pragma unroll
                for (int j = 0; j < 7; j++) {
                    const int br = (rb2 + 8 * j) * 32;
                    bf[pb][j][0] = Bb[br + kB0];
                    bf[pb][j][1] = Bb[br + kB1];
                }
            };

            loadFrags(0, 0);
#pragma unroll
            for (int ks = 0; ks < 4; ks++) {
                if (ks < 3) loadFrags(ks + 1, (ks + 1) & 1);
                const int pb = ks & 1;
#pragma unroll
                for (int i = 0; i < 2; i++)
#pragma unroll
                    for (int j = 0; j < 7; j++) {
                        asm volatile(
                            "mma.sync.aligned.m16n8k8.row.col.f32.tf32.tf32.f32 "
                            "{%0,%1,%2,%3}, {%4,%5,%6,%7}, {%8,%9}, {%0,%1,%2,%3};"
                            : "+f"(acc[i][j][0]), "+f"(acc[i][j][1]),
                              "+f"(acc[i][j][2]), "+f"(acc[i][j][3])
                            : "r"(af[pb][i].x), "r"(af[pb][i].y),
                              "r"(af[pb][i].z), "r"(af[pb][i].w),
                              "r"(bf[pb][j][0]), "r"(bf[pb][j][1]));
                    }
            }
            if (lane == 0) MBAR_ARRIVE(sb0 + 24 + 8*sA);   // A stage consumed
        }
        if (lane == 0) MBAR_ARRIVE(sb0 + 64 + 8*(cc & 1)); // B chunk consumed
    }

    // ---- epilogue: acc -> out[b][m][h0+wn][w] ----
    const int h = h0 + wn;
#pragma unroll
    for (int i = 0; i < 2; i++) {
        const int m = z * BM + wm * 32 + i * 16 + g;
        float* o0 = out + (((size_t)b * COUT + m    ) * PIX) + h * HW;
        float* o1 = out + (((size_t)b * COUT + m + 8) * PIX) + h * HW;
#pragma unroll
        for (int j = 0; j < 7; j++) {
            const int w = j * 8 + tig * 2;
            *reinterpret_cast<float2*>(o0 + w) = make_float2(acc[i][j][0], acc[i][j][1]);
            *reinterpret_cast<float2*>(o1 + w) = make_float2(acc[i][j][2], acc[i][j][3]);
        }
    }
}

extern "C" void kernel_launch(void* const* d_in, const int* in_sizes, int n_in,
                              void* d_out, int out_size)
{
    const float* x = (const float*)d_in[0];
    const float* W = (const float*)d_in[1];
    if (n_in >= 2 && in_sizes[0] == COUT * CIN * 9) { const float* t = x; x = W; W = t; }

    typedef CUresult (*EncodeFn)(CUtensorMap*, CUtensorMapDataType, cuuint32_t, void*,
                                 const cuuint64_t*, const cuuint64_t*, const cuuint32_t*,
                                 const cuuint32_t*, CUtensorMapInterleave, CUtensorMapSwizzle,
                                 CUtensorMapL2promotion, CUtensorMapFloatOOBfill);
    void* fnp = nullptr;
    cudaDriverEntryPointQueryResult qr;
    cudaGetDriverEntryPoint("cuTensorMapEncodeTiled", &fnp, cudaEnableDefault, &qr);
    EncodeFn encode = (EncodeFn)fnp;

    void *wt_ptr, *xp_ptr;
    cudaGetSymbolAddress(&wt_ptr, g_Wt);
    cudaGetSymbolAddress(&xp_ptr, g_xp);

    CUtensorMap tma_a{}, tma_b{};
    {   // A: packed g_Wt as [rows=9216][32 words], 128B rows, linear; box [32, 128]
        cuuint64_t dims[2]    = {32, 9216};
        cuuint64_t strides[1] = {128};
        cuuint32_t box[2]     = {32, 128};
        cuuint32_t es[2]      = {1, 1};
        encode(&tma_a, CU_TENSOR_MAP_DATA_TYPE_FLOAT32, 2, wt_ptr, dims, strides, box, es,
               CU_TENSOR_MAP_INTERLEAVE_NONE, CU_TENSOR_MAP_SWIZZLE_NONE,
               CU_TENSOR_MAP_L2_PROMOTION_L2_128B, CU_TENSOR_MAP_FLOAT_OOB_FILL_NONE);
    }
    {   // B: g_xp [b=32][hp=58][wp=58][c=128]; halo box [32 c, 58 w, 6 h, 1], SW128
        cuuint64_t dims[4]    = {CIN, HP, HP, NB};
        cuuint64_t strides[3] = {CIN * 4, (cuuint64_t)HP * CIN * 4, (cuuint64_t)HP * HP * CIN * 4};
        cuuint32_t box[4]     = {32, 58, 6, 1};
        cuuint32_t es[4]      = {1, 1, 1, 1};
        encode(&tma_b, CU_TENSOR_MAP_DATA_TYPE_FLOAT32, 4, xp_ptr, dims, strides, box, es,
               CU_TENSOR_MAP_INTERLEAVE_NONE, CU_TENSOR_MAP_SWIZZLE_128B,
               CU_TENSOR_MAP_L2_PROMOTION_L2_128B, CU_TENSOR_MAP_FLOAT_OOB_FILL_NONE);
    }

    wt_kernel<<<(COUT * KTOT + 255) / 256, 256>>>(W);
    xpad_kernel<<<NB * HW, 256>>>(x);
    xborder_kernel<<<(NB * 228 * CIN + 255) / 256, 256>>>();

    cudaFuncSetAttribute(conv_tc, cudaFuncAttributeMaxDynamicSharedMemorySize, SMEM_TOTAL);
    dim3 grid(14, 32, 2);
    conv_tc<<<grid, 512, SMEM_TOTAL>>>(tma_a, tma_b, (float*)d_out);
}

// round 9
// speedup vs baseline: 1.0766x; 1.0766x over previous
#include <cuda_runtime.h>
#include <cuda.h>
#include <cstdint>

#define CIN   128
#define COUT  256
#define HW    56
#define HP    58
#define PIX   (HW*HW)
#define KTOT  1152
#define NB    32

#define TILE_H   4
#define BM       128
#define A_BYTES  32768            // one chunk: 2 taps x 128 rows x 128B
#define B_BYTES  44544            // 348 rows x 128B (6x58 halo)
#define B_STRIDE 45056            // 1024-aligned
#define SMEM_TOTAL (1024 + 3*A_BYTES + 2*B_STRIDE)   // 189440
#define NACH     18               // A chunks (2 taps each)

// g_Wt: fragment-packed weights, z-outer:
// word idx: (((z*36 + t)*4 + ks)*8 + i8)*128 + lane*4 + w
__device__ uint32_t g_Wt[COUT * KTOT];
__device__ uint32_t g_xp[NB * HP * HP * CIN];   // [b][hp][wp][c], tf32 bits

__device__ __forceinline__ uint32_t smem_u32(const void* p) {
    uint32_t a;
    asm("{ .reg .u64 t; cvta.to.shared.u64 t, %1; cvt.u32.u64 %0, t; }" : "=r"(a) : "l"(p));
    return a;
}
__device__ __forceinline__ uint32_t f2tf(float v) {
    uint32_t r; asm("cvt.rna.tf32.f32 %0, %1;" : "=r"(r) : "f"(v)); return r;
}

#define MBAR_INIT(a, c) asm volatile("mbarrier.init.shared.b64 [%0], %1;" :: "r"(a), "r"(c) : "memory")
#define MBAR_TX(a, b)   asm volatile("mbarrier.arrive.expect_tx.shared.b64 _, [%0], %1;" :: "r"(a), "r"(b) : "memory")
#define MBAR_ARRIVE(a)  asm volatile("mbarrier.arrive.shared.b64 _, [%0];" :: "r"(a) : "memory")
#define MBAR_WAIT(a, p) do {                                                    \
    uint32_t _m = (a), _p = (p), _d;                                            \
    asm volatile("{\n\t.reg .pred q;\n\t"                                       \
        "mbarrier.try_wait.parity.acquire.cta.shared::cta.b64 q, [%1], %2;\n\t" \
        "selp.b32 %0, 1, 0, q;\n\t}" : "=r"(_d) : "r"(_m), "r"(_p) : "memory"); \
    if (!_d) {                                                                  \
        asm volatile("{\n\t.reg .pred Q;\n\t"                                   \
        "WL_%=:\n\t"                                                            \
        "mbarrier.try_wait.parity.acquire.cta.shared::cta.b64 Q, [%0], %1, 0x989680;\n\t" \
        "@Q bra.uni WD_%=;\n\t"                                                 \
        "bra.uni WL_%=;\n\t"                                                    \
        "WD_%=:\n\t}" :: "r"(_m), "r"(_p) : "memory");                          \
    } } while (0)

#define TMA_2D(d, tm, c0, c1, mb)                                               \
    asm volatile("cp.async.bulk.tensor.2d.shared::cta.global.tile.mbarrier::complete_tx::bytes " \
        "[%0], [%1, {%2, %3}], [%4];" :: "r"(d), "l"(tm), "r"(c0), "r"(c1), "r"(mb) : "memory")
#define TMA_4D(d, tm, c0, c1, c2, c3, mb)                                       \
    asm volatile("cp.async.bulk.tensor.4d.shared::cta.global.tile.mbarrier::complete_tx::bytes " \
        "[%0], [%1, {%2, %3, %4, %5}], [%6];" :: "r"(d), "l"(tm), "r"(c0), "r"(c1), "r"(c2), "r"(c3), "r"(mb) : "memory")

// ---- prepass: W -> fragment-packed g_Wt (z-outer) ----
// m = z*128 + i8*16 + g + (w&1)*8 ; kk = ks*8 + tig + ((w>>1)&1)*4 ; c = cc*32+kk
__global__ void wt_kernel(const float* __restrict__ W) {
    int idx = blockIdx.x * blockDim.x + threadIdx.x;
    if (idx >= COUT * KTOT) return;
    int w    = idx & 3;
    int lane = (idx >> 2) & 31;
    int i8   = (idx >> 7) & 7;
    int ks   = (idx >> 10) & 3;
    int zt   = idx >> 12;            // 0..71
    int z = zt / 36, t = zt - z * 36;
    int cc = t / 9, tap = t - cc * 9;
    int g = lane >> 2, tig = lane & 3;
    int m  = z * 128 + i8 * 16 + g + (w & 1) * 8;
    int kk = ks * 8 + tig + ((w >> 1) & 1) * 4;
    int c  = cc * 32 + kk;
    int dh = tap / 3, dw = tap - dh * 3;
    g_Wt[idx] = f2tf(W[((m * CIN + c) * 3 + dh) * 3 + dw]);
}
// ---- prepass: x[b][c][h][w] -> g_xp[b][h+1][w+1][c] (tf32, interior)
__global__ void xpad_kernel(const float* __restrict__ x) {
    __shared__ float sm[CIN * 57];
    int bx = blockIdx.x, b = bx / HW, h = bx - b * HW, tid = threadIdx.x;
    const float* xb = x + ((size_t)b * CIN) * PIX + h * HW;
    for (int i = tid; i < CIN * HW; i += 256) {
        int c = i / HW, w = i - c * HW;
        sm[c * 57 + w] = xb[c * PIX + w];
    }
    __syncthreads();
    uint32_t* xr = g_xp + ((size_t)(b * HP + h + 1)) * HP * CIN;
    for (int i = tid; i < HW * CIN; i += 256) {
        int w = i >> 7, c = i & 127;
        xr[(w + 1) * CIN + c] = f2tf(sm[c * 57 + w]);
    }
}
// ---- prepass: zero padded borders of g_xp
__global__ void xborder_kernel() {
    int idx = blockIdx.x * blockDim.x + threadIdx.x;
    if (idx >= NB * 228 * CIN) return;
    int c = idx & 127, r = idx >> 7, b = r / 228, cc = r - b * 228;
    int hp, wp;
    if (cc < 58)       { hp = 0;        wp = cc; }
    else if (cc < 116) { hp = 57;       wp = cc - 58; }
    else if (cc < 172) { hp = cc - 115; wp = 0; }
    else               { hp = cc - 171; wp = 57; }
    g_xp[((b * HP + hp) * HP + wp) * CIN + c] = 0u;
}

// ============================================================================
// Main: TMA-fed mma.sync tf32, 8 warps (64x56 tile), 2-tap A chunks, 3 stages.
//   CTA: M=128 (blockIdx.z half), N=224 (4 h-rows x 56 w)
//   smem: barriers | A[3][32KB] | B[2][44KB halo]
// ============================================================================
__global__ void __launch_bounds__(256, 1) conv_tc(
    const __grid_constant__ CUtensorMap tma_a,
    const __grid_constant__ CUtensorMap tma_b,
    float* __restrict__ out)
{
    extern __shared__ __align__(1024) uint8_t smem[];
    const uint32_t sb0 = smem_u32(smem);
    uint32_t* const smw = reinterpret_cast<uint32_t*>(smem);

    const int tid  = threadIdx.x;
    const int lane = tid & 31;
    const int g    = lane >> 2;
    const int tig  = lane & 3;
    const int warp = tid >> 5;
    const int wm   = warp >> 2;          // 0..1
    const int wn   = warp & 3;           // 0..3

    const int h0 = blockIdx.x * TILE_H;
    const int b  = blockIdx.y;
    const int z  = blockIdx.z;           // m half

    // barriers: afull[3]@0, aempty[3]@24, bfull[2]@48, bempty[2]@64
    if (tid == 0) {
        for (int s = 0; s < 3; s++) { MBAR_INIT(sb0 + 8*s, 1); MBAR_INIT(sb0 + 24 + 8*s, 8); }
        for (int s = 0; s < 2; s++) { MBAR_INIT(sb0 + 48 + 8*s, 1); MBAR_INIT(sb0 + 64 + 8*s, 8); }
    }
    __syncthreads();

    if (tid == 0) {   // prologue: A chunks 0,1 (taps 0-3) ; B chunk 0
        MBAR_TX(sb0 + 0, A_BYTES);
        TMA_2D(sb0 + 1024, &tma_a, 0, (z * 36) * 128, sb0 + 0);
        MBAR_TX(sb0 + 8, A_BYTES);
        TMA_2D(sb0 + 1024 + A_BYTES, &tma_a, 0, (z * 36 + 2) * 128, sb0 + 8);
        MBAR_TX(sb0 + 48, B_BYTES);
        TMA_4D(sb0 + 1024 + 3*A_BYTES, &tma_b, 0, 0, h0, b, sb0 + 48);
    }

    float acc[4][7][4];
#pragma unroll
    for (int i = 0; i < 4; i++)
#pragma unroll
        for (int j = 0; j < 7; j++)
#pragma unroll
            for (int e = 0; e < 4; e++) acc[i][j][e] = 0.f;

    uint4    af[2][4];
    uint32_t bf[2][7][2];

    for (int ch = 0; ch < NACH; ch++) {
        if (tid == 0 && ch + 2 < NACH) {    // prefetch A chunk ch+2 (stage u%3)
            const int u = ch + 2, s = u % 3;
            MBAR_WAIT(sb0 + 24 + 8*s, 1 ^ ((u / 3) & 1));
            MBAR_TX(sb0 + 8*s, A_BYTES);
            TMA_2D(sb0 + 1024 + s*A_BYTES, &tma_a, 0, (z * 36 + 2 * u) * 128, sb0 + 8*s);
        }
        const int sA = ch % 3;
        MBAR_WAIT(sb0 + 8*sA, (ch / 3) & 1);
        const uint4* Ach = reinterpret_cast<const uint4*>(smw + 256 + sA * (A_BYTES/4));

#pragma unroll 1
        for (int tp = 0; tp < 2; tp++) {
            const int t  = 2 * ch + tp;
            const int cc = t / 9, tap = t - cc * 9;

            if (tap == 0) {              // B chunk boundary
                if (tid == 0 && cc + 1 < 4) {
                    const int u = cc + 1, s = u & 1;
                    MBAR_WAIT(sb0 + 64 + 8*s, (u == 1) ? 1 : 0);
                    MBAR_TX(sb0 + 48 + 8*s, B_BYTES);
                    TMA_4D(sb0 + 1024 + 3*A_BYTES + s*B_STRIDE, &tma_b,
                           u*32, 0, h0, b, sb0 + 48 + 8*s);
                }
                MBAR_WAIT(sb0 + 48 + 8*(cc & 1), (cc >> 1) & 1);
            }
            const uint32_t* Bb = smw + 256 + 3*(A_BYTES/4) + (cc & 1)*(B_STRIDE/4);
            const uint4*    A4 = Ach + tp * 1024;

            const int dh = tap / 3, dw = tap - dh * 3;
            const int rb2 = (wn + dh) * 58 + dw + g;
            const int mb  = 4 * (rb2 & 7);

            auto loadFrags = [&](int ks, int pb) {
#pragma unroll
                for (int i = 0; i < 4; i++)
                    af[pb][i] = A4[(ks * 8 + wm * 4 + i) * 32 + lane];
                const int kb = 8 * ks;
                const int kB0 = (kb + tig) ^ mb, kB1 = (kb + tig + 4) ^ mb;
#pragma unroll
                for (int j = 0; j < 7; j++) {
                    const int br = (rb2 + 8 * j) * 32;
                    bf[pb][j][0] = Bb[br + kB0];
                    bf[pb][j][1] = Bb[br + kB1];
                }
            };

            loadFrags(0, 0);
#pragma unroll
            for (int ks = 0; ks < 4; ks++) {
                if (ks < 3) loadFrags(ks + 1, (ks + 1) & 1);
                const int pb = ks & 1;
#pragma unroll
                for (int i = 0; i < 4; i++)
#pragma unroll
                    for (int j = 0; j < 7; j++) {
                        asm volatile(
                            "mma.sync.aligned.m16n8k8.row.col.f32.tf32.tf32.f32 "
                            "{%0,%1,%2,%3}, {%4,%5,%6,%7}, {%8,%9}, {%0,%1,%2,%3};"
                            : "+f"(acc[i][j][0]), "+f"(acc[i][j][1]),
                              "+f"(acc[i][j][2]), "+f"(acc[i][j][3])
                            : "r"(af[pb][i].x), "r"(af[pb][i].y),
                              "r"(af[pb][i].z), "r"(af[pb][i].w),
                              "r"(bf[pb][j][0]), "r"(bf[pb][j][1]));
                    }
            }
            if (tap == 8 && lane == 0) MBAR_ARRIVE(sb0 + 64 + 8*(cc & 1));
        }
        if (lane == 0) MBAR_ARRIVE(sb0 + 24 + 8*sA);
    }

    // ---- epilogue: acc -> out[b][m][h0+wn][w] ----
    const int h = h0 + wn;
#pragma unroll
    for (int i = 0; i < 4; i++) {
        const int m = z * BM + wm * 64 + i * 16 + g;
        float* o0 = out + (((size_t)b * COUT + m    ) * PIX) + h * HW;
        float* o1 = out + (((size_t)b * COUT + m + 8) * PIX) + h * HW;
#pragma unroll
        for (int j = 0; j < 7; j++) {
            const int w = j * 8 + tig * 2;
            *reinterpret_cast<float2*>(o0 + w) = make_float2(acc[i][j][0], acc[i][j][1]);
            *reinterpret_cast<float2*>(o1 + w) = make_float2(acc[i][j][2], acc[i][j][3]);
        }
    }
}

extern "C" void kernel_launch(void* const* d_in, const int* in_sizes, int n_in,
                              void* d_out, int out_size)
{
    const float* x = (const float*)d_in[0];
    const float* W = (const float*)d_in[1];
    if (n_in >= 2 && in_sizes[0] == COUT * CIN * 9) { const float* t = x; x = W; W = t; }

    typedef CUresult (*EncodeFn)(CUtensorMap*, CUtensorMapDataType, cuuint32_t, void*,
                                 const cuuint64_t*, const cuuint64_t*, const cuuint32_t*,
                                 const cuuint32_t*, CUtensorMapInterleave, CUtensorMapSwizzle,
                                 CUtensorMapL2promotion, CUtensorMapFloatOOBfill);
    void* fnp = nullptr;
    cudaDriverEntryPointQueryResult qr;
    cudaGetDriverEntryPoint("cuTensorMapEncodeTiled", &fnp, cudaEnableDefault, &qr);
    EncodeFn encode = (EncodeFn)fnp;

    void *wt_ptr, *xp_ptr;
    cudaGetSymbolAddress(&wt_ptr, g_Wt);
    cudaGetSymbolAddress(&xp_ptr, g_xp);

    CUtensorMap tma_a{}, tma_b{};
    {   // A: packed g_Wt as [rows=9216][32 words], 128B rows, linear; box [32, 256]
        cuuint64_t dims[2]    = {32, 9216};
        cuuint64_t strides[1] = {128};
        cuuint32_t box[2]     = {32, 256};
        cuuint32_t es[2]      = {1, 1};
        encode(&tma_a, CU_TENSOR_MAP_DATA_TYPE_FLOAT32, 2, wt_ptr, dims, strides, box, es,
               CU_TENSOR_MAP_INTERLEAVE_NONE, CU_TENSOR_MAP_SWIZZLE_NONE,
               CU_TENSOR_MAP_L2_PROMOTION_L2_128B, CU_TENSOR_MAP_FLOAT_OOB_FILL_NONE);
    }
    {   // B: g_xp [b=32][hp=58][wp=58][c=128]; halo box [32 c, 58 w, 6 h, 1], SW128
        cuuint64_t dims[4]    = {CIN, HP, HP, NB};
        cuuint64_t strides[3] = {CIN * 4, (cuuint64_t)HP * CIN * 4, (cuuint64_t)HP * HP * CIN * 4};
        cuuint32_t box[4]     = {32, 58, 6, 1};
        cuuint32_t es[4]      = {1, 1, 1, 1};
        encode(&tma_b, CU_TENSOR_MAP_DATA_TYPE_FLOAT32, 4, xp_ptr, dims, strides, box, es,
               CU_TENSOR_MAP_INTERLEAVE_NONE, CU_TENSOR_MAP_SWIZZLE_128B,
               CU_TENSOR_MAP_L2_PROMOTION_L2_128B, CU_TENSOR_MAP_FLOAT_OOB_FILL_NONE);
    }

    wt_kernel<<<(COUT * KTOT + 255) / 256, 256>>>(W);
    xpad_kernel<<<NB * HW, 256>>>(x);
    xborder_kernel<<<(NB * 228 * CIN + 255) / 256, 256>>>();

    cudaFuncSetAttribute(conv_tc, cudaFuncAttributeMaxDynamicSharedMemorySize, SMEM_TOTAL);
    dim3 grid(14, 32, 2);
    conv_tc<<<grid, 256, SMEM_TOTAL>>>(tma_a, tma_b, (float*)d_out);
}